// round 14
// baseline (speedup 1.0000x reference)
#include <cuda_runtime.h>

// Sobel edge magnitude + channel mean.
// x: [B=16, C=64, H=256, W=256] f32 -> out: [B,1,H,W] f32
//
// Separable: p_i = x[i][w+1]-x[i][w-1], q_i = x[i][w-1]+2x[i][w]+x[i][w+1]
//   gx(r) = p_r + 2 p_{r+1} + p_{r+2},   gy(r) = q_{r+2} - q_r
//
// R14 changes vs R12/R13:
//  - RR 4 -> 2: finer block granularity fixes wave quantization (4096 blocks
//    @ 592 concurrent -> 3.5-unit makespan vs 4.0) WITHOUT the partial-buffer
//    + reduce-kernel tax that sank R13 (blocks keep all 64 channels and write
//    final output directly).
//  - Smaller per-channel state (acc 8, vv 16, hl 4 regs) lets REGISTER
//    accumulators fit 64 regs -> 4 CTAs/SM, dropping R12's smem-RMW L1 load.

#define BB 16
#define CC 64
#define HH 256
#define WW 256
#define RR 2          // output rows per tile
#define NROWS (RR + 2)
#define NWARPS 8      // warps per block (channel stride)
#define TW 128        // columns per warp tile (32 lanes * 4)
#define HSTRIPS (HH / RR)
#define KITERS (CC / NWARPS)

typedef unsigned long long u64;

__device__ __forceinline__ float sqrt_approx(float v) {
    float y; asm("sqrt.approx.f32 %0, %1;" : "=f"(y) : "f"(v)); return y;
}
__device__ __forceinline__ u64 pk(float lo, float hi) {
    u64 r; asm("mov.b64 %0, {%1, %2};" : "=l"(r) : "f"(lo), "f"(hi)); return r;
}
__device__ __forceinline__ void upk(float& lo, float& hi, u64 v) {
    asm("mov.b64 {%0, %1}, %2;" : "=f"(lo), "=f"(hi) : "l"(v));
}
__device__ __forceinline__ u64 add2(u64 a, u64 b) {
    u64 r; asm("add.rn.f32x2 %0, %1, %2;" : "=l"(r) : "l"(a), "l"(b)); return r;
}
__device__ __forceinline__ u64 fma2(u64 a, u64 b, u64 c) {
    u64 r; asm("fma.rn.f32x2 %0, %1, %2, %3;" : "=l"(r) : "l"(a), "l"(b), "l"(c)); return r;
}
__device__ __forceinline__ void prefetch_l2(const float* p) {
    asm volatile("prefetch.global.L2 [%0];" :: "l"(p));
}

__global__ __launch_bounds__(256, 4)
void sobel_mean_kernel(const float* __restrict__ x, float* __restrict__ out) {
    const int wq   = blockIdx.x;   // column tile: 0..1
    const int hs   = blockIdx.y;   // row strip:   0..127
    const int b    = blockIdx.z;
    const int tid  = threadIdx.x;
    const int wid  = tid >> 5;
    const int lane = tid & 31;

    const int gw4 = wq * TW + lane * 4;
    const int gh0 = hs * RR;

    const bool top_oob = (hs == 0);
    const bool bot_oob = (hs == HSTRIPS - 1);
    const bool has_left  = (gw4 != 0);
    const bool has_right = (gw4 + 4 != WW);

    // One merged edge-halo load per row: lane0 -> col gw4-1, lane31 -> gw4+4.
    const bool edge_ld = (lane == 0 && has_left) || (lane == 31 && has_right);
    const int  ha      = (lane == 0) ? (gw4 - 1) : (gw4 + 4);

    __shared__ float s_acc[NWARPS][RR * TW];   // 8 KB: per-warp partials

    const u64 TWO2 = pk(2.0f, 2.0f);
    const u64 NEG1 = pk(-1.0f, -1.0f);
    const u64 EPS2 = pk(1e-12f, 1e-12f);
    const unsigned FULL = 0xFFFFFFFFu;

    float4 acc[RR];
#pragma unroll
    for (int r = 0; r < RR; r++) acc[r] = make_float4(0.f, 0.f, 0.f, 0.f);

    const float* __restrict__ plane0 =
        x + ((size_t)(b * CC + wid)) * (HH * WW);
    const size_t cstride = (size_t)NWARPS * (HH * WW);

#pragma unroll 1
    for (int k = 0; k < KITERS; k++) {
        const float* __restrict__ plane = plane0 + (size_t)k * cstride;

        // ---- Phase 1: batch all loads for the 4-row strip ----
        float4 vv[NROWS];
        float  hl[NROWS];
#pragma unroll
        for (int i = 0; i < NROWS; i++) {
            const int gh = gh0 - 1 + i;
            const bool oob = (i == 0 && top_oob) || (i == NROWS - 1 && bot_oob);
            const float* __restrict__ row = plane + gh * WW;
            vv[i] = make_float4(0.f, 0.f, 0.f, 0.f);
            hl[i] = 0.f;
            if (!oob) {
                vv[i] = *reinterpret_cast<const float4*>(row + gw4);
                if (edge_ld) hl[i] = row[ha];
            }
        }

        // Prefetch next channel's strip into L2 (no regs held).
        if (k + 1 < KITERS) {
            const float* __restrict__ np = plane + cstride;
#pragma unroll
            for (int i = 0; i < NROWS; i++) {
                const int gh = gh0 - 1 + i;
                const bool oob = (i == 0 && top_oob) || (i == NROWS - 1 && bot_oob);
                if (!oob) prefetch_l2(np + gh * WW + gw4);
            }
        }

        // ---- Phase 2: rolling p/q window; neighbors via SHFL ----
        u64 p0l = 0, p0h = 0, p1l = 0, p1h = 0;
        u64 q0l = 0, q0h = 0, q1l = 0, q1h = 0;
#pragma unroll
        for (int i = 0; i < NROWS; i++) {
            const float4 v = vv[i];
            float lft = __shfl_up_sync(FULL, v.w, 1);
            float rgt = __shfl_down_sync(FULL, v.x, 1);
            if (lane == 0)  lft = hl[i];
            if (lane == 31) rgt = hl[i];

            const u64 cl = pk(v.x, v.y);
            const u64 ch = pk(v.z, v.w);
            const u64 ll = pk(lft, v.x);
            const u64 lh = pk(v.y, v.z);
            const u64 rh = pk(v.w, rgt);

            const u64 pl = fma2(NEG1, ll, lh);            // r - l
            const u64 ph = fma2(NEG1, lh, rh);
            const u64 ql = add2(fma2(cl, TWO2, ll), lh);  // l + 2c + r
            const u64 qh = add2(fma2(ch, TWO2, lh), rh);

            if (i >= 2) {
                const int r = i - 2;
                const u64 gxl = add2(fma2(p1l, TWO2, p0l), pl);
                const u64 gxh = add2(fma2(p1h, TWO2, p0h), ph);
                const u64 gyl = fma2(NEG1, q0l, ql);
                const u64 gyh = fma2(NEG1, q0h, qh);
                const u64 m_l = fma2(gxl, gxl, fma2(gyl, gyl, EPS2));
                const u64 m_h = fma2(gxh, gxh, fma2(gyh, gyh, EPS2));
                float m0, m1, m2, m3;
                upk(m0, m1, m_l);
                upk(m2, m3, m_h);
                acc[r].x += sqrt_approx(m0);
                acc[r].y += sqrt_approx(m1);
                acc[r].z += sqrt_approx(m2);
                acc[r].w += sqrt_approx(m3);
            }
            p0l = p1l; p0h = p1h; p1l = pl; p1h = ph;
            q0l = q1l; q0h = q1h; q1l = ql; q1h = qh;
        }
    }

    // Stage per-warp partials, then block-reduce across the 8 warps.
#pragma unroll
    for (int r = 0; r < RR; r++)
        *reinterpret_cast<float4*>(&s_acc[wid][r * TW + lane * 4]) = acc[r];
    __syncthreads();

    const float inv = 1.0f / (float)CC;
    {
        const int px = tid;                    // RR*TW == 256 == blockDim
        float s = 0.f;
#pragma unroll
        for (int w = 0; w < NWARPS; w++) s += s_acc[w][px];
        const int r   = px / TW;
        const int col = px % TW;
        out[((size_t)b * HH + (gh0 + r)) * WW + wq * TW + col] = s * inv;
    }
}

extern "C" void kernel_launch(void* const* d_in, const int* in_sizes, int n_in,
                              void* d_out, int out_size) {
    const float* x = (const float*)d_in[0];
    float* out = (float*)d_out;
    dim3 grid(WW / TW, HSTRIPS, BB);   // (2, 128, 16) = 4096 blocks
    sobel_mean_kernel<<<grid, 256>>>(x, out);
}

// round 15
// speedup vs baseline: 1.1399x; 1.1399x over previous
#include <cuda_runtime.h>

// Sobel edge magnitude + channel mean.
// x: [B=16, C=64, H=256, W=256] f32 -> out: [B,1,H,W] f32
//
// Separable: p_i = x[i][w+1]-x[i][w-1], q_i = x[i][w-1]+2x[i][w]+x[i][w+1]
//   gx(r) = p_r + 2 p_{r+1} + p_{r+2},   gy(r) = q_{r+2} - q_r
//
// R15 changes vs R12 (kernel 51.1us):
//  - MUFU pressure halved: 268M element-sqrts = 8.4M warp-MUFU at rt 8/SMSP
//    is ~113K chip-cycles -- the invisible binding pipe. The low pixel-pair
//    of each row now computes sqrt(m) = m * rsqrt(m) on the FMA pipe
//    (bit-hack seed + 2 packed f32x2 Newton iters, rel err ~5e-6); the high
//    pair stays on MUFU. Pipes balance at ~28us MUFU / ~31us FMA.

#define BB 16
#define CC 64
#define HH 256
#define WW 256
#define RR 4          // output rows per tile
#define NROWS (RR + 2)
#define NWARPS 8      // warps per block (channel stride)
#define TW 128        // columns per warp tile (32 lanes * 4)
#define HSTRIPS (HH / RR)
#define KITERS (CC / NWARPS)

typedef unsigned long long u64;

__device__ __forceinline__ float sqrt_approx(float v) {
    float y; asm("sqrt.approx.f32 %0, %1;" : "=f"(y) : "f"(v)); return y;
}
__device__ __forceinline__ u64 pk(float lo, float hi) {
    u64 r; asm("mov.b64 %0, {%1, %2};" : "=l"(r) : "f"(lo), "f"(hi)); return r;
}
__device__ __forceinline__ void upk(float& lo, float& hi, u64 v) {
    asm("mov.b64 {%0, %1}, %2;" : "=f"(lo), "=f"(hi) : "l"(v));
}
__device__ __forceinline__ u64 add2(u64 a, u64 b) {
    u64 r; asm("add.rn.f32x2 %0, %1, %2;" : "=l"(r) : "l"(a), "l"(b)); return r;
}
__device__ __forceinline__ u64 mul2(u64 a, u64 b) {
    u64 r; asm("mul.rn.f32x2 %0, %1, %2;" : "=l"(r) : "l"(a), "l"(b)); return r;
}
__device__ __forceinline__ u64 fma2(u64 a, u64 b, u64 c) {
    u64 r; asm("fma.rn.f32x2 %0, %1, %2, %3;" : "=l"(r) : "l"(a), "l"(b), "l"(c)); return r;
}
__device__ __forceinline__ void prefetch_l2(const float* p) {
    asm volatile("prefetch.global.L2 [%0];" :: "l"(p));
}
// Packed rsqrt seed: y0 = bitcast(0x5f3759df - (bitcast(m) >> 1)) per half.
__device__ __forceinline__ u64 rsqrt_seed2(u64 m) {
    unsigned lo, hi;
    asm("mov.b64 {%0, %1}, %2;" : "=r"(lo), "=r"(hi) : "l"(m));
    lo = 0x5f3759dfu - (lo >> 1);
    hi = 0x5f3759dfu - (hi >> 1);
    u64 y; asm("mov.b64 %0, {%1, %2};" : "=l"(y) : "r"(lo), "r"(hi));
    return y;
}

__global__ __launch_bounds__(256, 4)
void sobel_mean_kernel(const float* __restrict__ x, float* __restrict__ out) {
    const int wq   = blockIdx.x;   // column tile: 0..1
    const int hs   = blockIdx.y;   // row strip:   0..63
    const int b    = blockIdx.z;
    const int tid  = threadIdx.x;
    const int wid  = tid >> 5;
    const int lane = tid & 31;

    const int gw4 = wq * TW + lane * 4;
    const int gh0 = hs * RR;

    const bool top_oob = (hs == 0);
    const bool bot_oob = (hs == HSTRIPS - 1);
    const bool has_left  = (gw4 != 0);
    const bool has_right = (gw4 + 4 != WW);

    // One merged edge-halo load per row: lane0 -> col gw4-1, lane31 -> gw4+4.
    const bool edge_ld = (lane == 0 && has_left) || (lane == 31 && has_right);
    const int  ha      = (lane == 0) ? (gw4 - 1) : (gw4 + 4);

    __shared__ float s_acc[NWARPS][RR * TW];   // 16 KB: per-warp partials

    // Zero this block's accumulator region.
#pragma unroll
    for (int j = 0; j < (NWARPS * RR * TW) / (256 * 4); j++) {
        const int e = (tid + 256 * j) * 4;
        *reinterpret_cast<float4*>(&s_acc[0][0] + e) =
            make_float4(0.f, 0.f, 0.f, 0.f);
    }
    __syncthreads();

    float* my_acc = &s_acc[wid][lane * 4];

    const u64 TWO2 = pk(2.0f, 2.0f);
    const u64 NEG1 = pk(-1.0f, -1.0f);
    const u64 EPS2 = pk(1e-12f, 1e-12f);
    const u64 NEGH = pk(-0.5f, -0.5f);
    const u64 C32  = pk(1.5f, 1.5f);
    const unsigned FULL = 0xFFFFFFFFu;

    const float* __restrict__ plane0 =
        x + ((size_t)(b * CC + wid)) * (HH * WW);
    const size_t cstride = (size_t)NWARPS * (HH * WW);

#pragma unroll 1
    for (int k = 0; k < KITERS; k++) {
        const float* __restrict__ plane = plane0 + (size_t)k * cstride;

        // ---- Phase 1: batch all loads for the 6-row strip ----
        float4 vv[NROWS];
        float  hl[NROWS];
#pragma unroll
        for (int i = 0; i < NROWS; i++) {
            const int gh = gh0 - 1 + i;
            const bool oob = (i == 0 && top_oob) || (i == NROWS - 1 && bot_oob);
            const float* __restrict__ row = plane + gh * WW;
            vv[i] = make_float4(0.f, 0.f, 0.f, 0.f);
            hl[i] = 0.f;
            if (!oob) {
                vv[i] = *reinterpret_cast<const float4*>(row + gw4);
                if (edge_ld) hl[i] = row[ha];
            }
        }

        // Prefetch next channel's strip into L2 (no regs held).
        if (k + 1 < KITERS) {
            const float* __restrict__ np = plane + cstride;
#pragma unroll
            for (int i = 0; i < NROWS; i++) {
                const int gh = gh0 - 1 + i;
                const bool oob = (i == 0 && top_oob) || (i == NROWS - 1 && bot_oob);
                if (!oob) prefetch_l2(np + gh * WW + gw4);
            }
        }

        // ---- Phase 2: rolling p/q window; neighbors via SHFL ----
        u64 p0l = 0, p0h = 0, p1l = 0, p1h = 0;
        u64 q0l = 0, q0h = 0, q1l = 0, q1h = 0;
#pragma unroll
        for (int i = 0; i < NROWS; i++) {
            const float4 v = vv[i];
            float lft = __shfl_up_sync(FULL, v.w, 1);
            float rgt = __shfl_down_sync(FULL, v.x, 1);
            if (lane == 0)  lft = hl[i];
            if (lane == 31) rgt = hl[i];

            const u64 cl = pk(v.x, v.y);
            const u64 ch = pk(v.z, v.w);
            const u64 ll = pk(lft, v.x);
            const u64 lh = pk(v.y, v.z);
            const u64 rh = pk(v.w, rgt);

            const u64 pl = fma2(NEG1, ll, lh);            // r - l
            const u64 ph = fma2(NEG1, lh, rh);
            const u64 ql = add2(fma2(cl, TWO2, ll), lh);  // l + 2c + r
            const u64 qh = add2(fma2(ch, TWO2, lh), rh);

            if (i >= 2) {
                const int r = i - 2;
                const u64 gxl = add2(fma2(p1l, TWO2, p0l), pl);
                const u64 gxh = add2(fma2(p1h, TWO2, p0h), ph);
                const u64 gyl = fma2(NEG1, q0l, ql);
                const u64 gyh = fma2(NEG1, q0h, qh);
                const u64 m_l = fma2(gxl, gxl, fma2(gyl, gyl, EPS2));
                const u64 m_h = fma2(gxh, gxh, fma2(gyh, gyh, EPS2));

                // Low pair: sqrt on FMA pipe (seed + 2 packed Newton iters).
                u64 y = rsqrt_seed2(m_l);
                const u64 nh = mul2(m_l, NEGH);           // -m/2
                u64 t = mul2(y, y);
                y = mul2(y, fma2(nh, t, C32));
                t = mul2(y, y);
                y = mul2(y, fma2(nh, t, C32));
                const u64 magl = mul2(m_l, y);            // m * rsqrt(m)

                // High pair: MUFU sqrt.
                float m2v, m3v;
                upk(m2v, m3v, m_h);
                float g0, g1;
                upk(g0, g1, magl);

                float4 cur = *reinterpret_cast<float4*>(my_acc + r * TW);
                cur.x += g0;
                cur.y += g1;
                cur.z += sqrt_approx(m2v);
                cur.w += sqrt_approx(m3v);
                *reinterpret_cast<float4*>(my_acc + r * TW) = cur;
            }
            p0l = p1l; p0h = p1h; p1l = pl; p1h = ph;
            q0l = q1l; q0h = q1h; q1l = ql; q1h = qh;
        }
    }

    __syncthreads();

    // Block-reduce the 8 per-warp partials and write out.
    const float inv = 1.0f / (float)CC;
#pragma unroll
    for (int j = 0; j < (RR * TW) / 256; j++) {
        const int px = tid + 256 * j;          // 0..511
        float s = 0.f;
#pragma unroll
        for (int w = 0; w < NWARPS; w++) s += s_acc[w][px];
        const int r   = px / TW;
        const int col = px % TW;
        out[((size_t)b * HH + (gh0 + r)) * WW + wq * TW + col] = s * inv;
    }
}

extern "C" void kernel_launch(void* const* d_in, const int* in_sizes, int n_in,
                              void* d_out, int out_size) {
    const float* x = (const float*)d_in[0];
    float* out = (float*)d_out;
    dim3 grid(WW / TW, HSTRIPS, BB);   // (2, 64, 16) = 2048 blocks
    sobel_mean_kernel<<<grid, 256>>>(x, out);
}

// round 16
// speedup vs baseline: 1.1495x; 1.0084x over previous
#include <cuda_runtime.h>

// Sobel edge magnitude + channel mean.
// x: [B=16, C=64, H=256, W=256] f32 -> out: [B,1,H,W] f32
//
// Separable: p_i = x[i][w+1]-x[i][w-1], q_i = x[i][w-1]+2x[i][w]+x[i][w+1]
//   gx(r) = p_r + 2 p_{r+1} + p_{r+2},   gy(r) = q_{r+2} - q_r
//
// R16 = R11 (best, 52.0us: register acc, 3 CTA/SM, shfl halos, merged edge
// LDG, 6-row upfront batch) with two memory-pipeline sharpenings:
//  - L2 prefetch distance 1 -> 2 strips (consume becomes a 234cyc L2 hit
//    instead of racing 577+cyc DRAM latency). Prologue prefetches strip 1.
//  - Row loads via ld.global.nc (__ldg): read-only path, no L1 allocation
//    churn for zero-reuse lines.

#define BB 16
#define CC 64
#define HH 256
#define WW 256
#define RR 4          // output rows per tile
#define NROWS (RR + 2)
#define NWARPS 8      // warps per block (channel stride)
#define TW 128        // columns per warp tile (32 lanes * 4)
#define HSTRIPS (HH / RR)
#define KITERS (CC / NWARPS)

typedef unsigned long long u64;

__device__ __forceinline__ float sqrt_approx(float v) {
    float y; asm("sqrt.approx.f32 %0, %1;" : "=f"(y) : "f"(v)); return y;
}
__device__ __forceinline__ u64 pk(float lo, float hi) {
    u64 r; asm("mov.b64 %0, {%1, %2};" : "=l"(r) : "f"(lo), "f"(hi)); return r;
}
__device__ __forceinline__ void upk(float& lo, float& hi, u64 v) {
    asm("mov.b64 {%0, %1}, %2;" : "=f"(lo), "=f"(hi) : "l"(v));
}
__device__ __forceinline__ u64 add2(u64 a, u64 b) {
    u64 r; asm("add.rn.f32x2 %0, %1, %2;" : "=l"(r) : "l"(a), "l"(b)); return r;
}
__device__ __forceinline__ u64 fma2(u64 a, u64 b, u64 c) {
    u64 r; asm("fma.rn.f32x2 %0, %1, %2, %3;" : "=l"(r) : "l"(a), "l"(b), "l"(c)); return r;
}
__device__ __forceinline__ void prefetch_l2(const float* p) {
    asm volatile("prefetch.global.L2 [%0];" :: "l"(p));
}

__global__ __launch_bounds__(256, 3)
void sobel_mean_kernel(const float* __restrict__ x, float* __restrict__ out) {
    const int wq   = blockIdx.x;   // column tile: 0..1
    const int hs   = blockIdx.y;   // row strip:   0..63
    const int b    = blockIdx.z;
    const int tid  = threadIdx.x;
    const int wid  = tid >> 5;
    const int lane = tid & 31;

    const int gw4 = wq * TW + lane * 4;
    const int gh0 = hs * RR;

    const bool top_oob = (hs == 0);
    const bool bot_oob = (hs == HSTRIPS - 1);
    const bool has_left  = (gw4 != 0);
    const bool has_right = (gw4 + 4 != WW);

    // One merged edge-halo load per row: lane0 -> col gw4-1, lane31 -> gw4+4.
    const bool edge_ld = (lane == 0 && has_left) || (lane == 31 && has_right);
    const int  ha      = (lane == 0) ? (gw4 - 1) : (gw4 + 4);

    __shared__ float s_acc[NWARPS][RR * TW];   // 16 KB

    const u64 TWO2 = pk(2.0f, 2.0f);
    const u64 NEG1 = pk(-1.0f, -1.0f);
    const u64 EPS2 = pk(1e-12f, 1e-12f);
    const unsigned FULL = 0xFFFFFFFFu;

    float4 acc[RR];
#pragma unroll
    for (int r = 0; r < RR; r++) acc[r] = make_float4(0.f, 0.f, 0.f, 0.f);

    const float* __restrict__ plane0 =
        x + ((size_t)(b * CC + wid)) * (HH * WW);
    const size_t cstride = (size_t)NWARPS * (HH * WW);

    // Prologue: prefetch strip k=1 (distance-2 steady state starts below).
    {
        const float* __restrict__ np = plane0 + cstride;
#pragma unroll
        for (int i = 0; i < NROWS; i++) {
            const int gh = gh0 - 1 + i;
            const bool oob = (i == 0 && top_oob) || (i == NROWS - 1 && bot_oob);
            if (!oob) prefetch_l2(np + gh * WW + gw4);
        }
    }

#pragma unroll 1
    for (int k = 0; k < KITERS; k++) {
        const float* __restrict__ plane = plane0 + (size_t)k * cstride;

        // ---- Phase 1: batch all loads for the 6-row strip ----
        float4 vv[NROWS];
        float  hl[NROWS];
#pragma unroll
        for (int i = 0; i < NROWS; i++) {
            const int gh = gh0 - 1 + i;
            const bool oob = (i == 0 && top_oob) || (i == NROWS - 1 && bot_oob);
            const float* __restrict__ row = plane + gh * WW;
            vv[i] = make_float4(0.f, 0.f, 0.f, 0.f);
            hl[i] = 0.f;
            if (!oob) {
                vv[i] = __ldg(reinterpret_cast<const float4*>(row + gw4));
                if (edge_ld) hl[i] = __ldg(row + ha);
            }
        }

        // Prefetch strip k+2 into L2 (distance 2; no regs held).
        if (k + 2 < KITERS) {
            const float* __restrict__ np = plane + 2 * cstride;
#pragma unroll
            for (int i = 0; i < NROWS; i++) {
                const int gh = gh0 - 1 + i;
                const bool oob = (i == 0 && top_oob) || (i == NROWS - 1 && bot_oob);
                if (!oob) prefetch_l2(np + gh * WW + gw4);
            }
        }

        // ---- Phase 2: rolling p/q window; neighbors via SHFL ----
        u64 p0l = 0, p0h = 0, p1l = 0, p1h = 0;
        u64 q0l = 0, q0h = 0, q1l = 0, q1h = 0;
#pragma unroll
        for (int i = 0; i < NROWS; i++) {
            const float4 v = vv[i];
            float lft = __shfl_up_sync(FULL, v.w, 1);
            float rgt = __shfl_down_sync(FULL, v.x, 1);
            if (lane == 0)  lft = hl[i];
            if (lane == 31) rgt = hl[i];

            const u64 cl = pk(v.x, v.y);
            const u64 ch = pk(v.z, v.w);
            const u64 ll = pk(lft, v.x);
            const u64 lh = pk(v.y, v.z);
            const u64 rh = pk(v.w, rgt);

            const u64 pl = fma2(NEG1, ll, lh);            // r - l
            const u64 ph = fma2(NEG1, lh, rh);
            const u64 ql = add2(fma2(cl, TWO2, ll), lh);  // l + 2c + r
            const u64 qh = add2(fma2(ch, TWO2, lh), rh);

            if (i >= 2) {
                const int r = i - 2;
                const u64 gxl = add2(fma2(p1l, TWO2, p0l), pl);
                const u64 gxh = add2(fma2(p1h, TWO2, p0h), ph);
                const u64 gyl = fma2(NEG1, q0l, ql);
                const u64 gyh = fma2(NEG1, q0h, qh);
                const u64 m_l = fma2(gxl, gxl, fma2(gyl, gyl, EPS2));
                const u64 m_h = fma2(gxh, gxh, fma2(gyh, gyh, EPS2));
                float m0, m1, m2, m3;
                upk(m0, m1, m_l);
                upk(m2, m3, m_h);
                acc[r].x += sqrt_approx(m0);
                acc[r].y += sqrt_approx(m1);
                acc[r].z += sqrt_approx(m2);
                acc[r].w += sqrt_approx(m3);
            }
            p0l = p1l; p0h = p1h; p1l = pl; p1h = ph;
            q0l = q1l; q0h = q1h; q1l = ql; q1h = qh;
        }
    }

    // Stage per-warp partials, then block-reduce across the 8 warps.
#pragma unroll
    for (int r = 0; r < RR; r++)
        *reinterpret_cast<float4*>(&s_acc[wid][r * TW + lane * 4]) = acc[r];
    __syncthreads();

    const float inv = 1.0f / (float)CC;
#pragma unroll
    for (int j = 0; j < (RR * TW) / 256; j++) {
        const int px = tid + 256 * j;          // 0..511
        float s = 0.f;
#pragma unroll
        for (int w = 0; w < NWARPS; w++) s += s_acc[w][px];
        const int r   = px / TW;
        const int col = px % TW;
        out[((size_t)b * HH + (gh0 + r)) * WW + wq * TW + col] = s * inv;
    }
}

extern "C" void kernel_launch(void* const* d_in, const int* in_sizes, int n_in,
                              void* d_out, int out_size) {
    const float* x = (const float*)d_in[0];
    float* out = (float*)d_out;
    dim3 grid(WW / TW, HSTRIPS, BB);   // (2, 64, 16) = 2048 blocks
    sobel_mean_kernel<<<grid, 256>>>(x, out);
}